// round 3
// baseline (speedup 1.0000x reference)
#include <cuda_runtime.h>
#include <cuda_bf16.h>
#include <math.h>

// Problem constants
#define B_  32
#define C_  256
#define O_  256
#define HH  56
#define WW  56
#define CH_ 4

// ---------------- device scratch (static: no dynamic allocation allowed) ----
__device__ float g_pooled[B_ * C_];            // [b][c]
__device__ float g_kern  [B_ * C_ * CH_];      // [b][c*4+ch]
__device__ float g_wT    [C_ * 9 * O_];        // [c][ij][o]  (transposed weight)
__device__ float g_dynw  [(size_t)B_ * C_ * 9 * O_]; // [b][c][ij][o]  (75.5 MB)

// ---------------- K1: global average pool ----------------------------------
__global__ void pool_kernel(const float* __restrict__ x) {
    int bc = blockIdx.x;                       // b*256 + c
    const float* p = x + (size_t)bc * (HH * WW);
    float s = 0.f;
    for (int i = threadIdx.x; i < HH * WW; i += 256) s += p[i];
    __shared__ float red[256];
    red[threadIdx.x] = s;
    __syncthreads();
    for (int st = 128; st > 0; st >>= 1) {
        if (threadIdx.x < st) red[threadIdx.x] += red[threadIdx.x + st];
        __syncthreads();
    }
    if (threadIdx.x == 0) g_pooled[bc] = red[0] * (1.f / (HH * WW));
}

// ---------------- K2: fc1(relu) + fc2 fused, one block per batch -----------
__global__ void fc_kernel(const float* __restrict__ fc1w,
                          const float* __restrict__ fc2w,
                          const float* __restrict__ fc2b) {
    int b = blockIdx.x, t = threadIdx.x;       // 256 threads
    __shared__ float sp[C_], sh[C_];
    sp[t] = g_pooled[b * C_ + t];
    __syncthreads();
    float d = 0.f;
    const float* w1 = fc1w + t * C_;
    #pragma unroll 8
    for (int k = 0; k < C_; k++) d += sp[k] * w1[k];
    sh[t] = fmaxf(d, 0.f);
    __syncthreads();
    #pragma unroll
    for (int r = 0; r < 4; r++) {
        int j = r * 256 + t;                   // j < 1024
        const float* w2 = fc2w + j * C_;
        float d2 = fc2b[j];
        #pragma unroll 8
        for (int k = 0; k < C_; k++) d2 += sh[k] * w2[k];
        g_kern[b * (C_ * CH_) + j] = d2;
    }
}

// ---------------- K2.5: transpose static weight [o][c][ij] -> [c][ij][o] ----
__global__ void wt_kernel(const float* __restrict__ w) {
    int e = blockIdx.x * 256 + threadIdx.x;    // < 256*256*9 = 589824
    int o = e / (C_ * 9);
    int rem = e - o * (C_ * 9);                // c*9+ij
    g_wT[(size_t)rem * O_ + o] = w[e];
}

// ---------------- K3: dynamic weight generation -----------------------------
// dynw[b][c][ij][o] = sigmoid( sum_ch kern[b,c,ch]*cog[o,ch,ij] ) * weight[o,c,ij]
__global__ void dynw_kernel(const float* __restrict__ cog) {
    int blk = blockIdx.x;                      // 32*32 blocks
    int b = blk >> 5;
    int cg = blk & 31;                         // c group of 8
    int o = threadIdx.x;                       // 256 threads
    __shared__ float cogs[CH_ * 9 * O_];       // [ch*9+ij][o], 36.9 KB
    for (int e = o; e < CH_ * 9 * O_; e += 256) {
        int k  = e >> 8;                       // ch*9+ij
        int oo = e & 255;
        cogs[e] = cog[oo * (CH_ * 9) + k];
    }
    __syncthreads();
    for (int cl = 0; cl < 8; cl++) {
        int c = cg * 8 + cl;
        const float* kp = g_kern + b * (C_ * CH_) + c * CH_;
        float kv0 = kp[0], kv1 = kp[1], kv2 = kp[2], kv3 = kp[3];
        #pragma unroll
        for (int ij = 0; ij < 9; ij++) {
            float s = kv0 * cogs[(0 * 9 + ij) * O_ + o]
                    + kv1 * cogs[(1 * 9 + ij) * O_ + o]
                    + kv2 * cogs[(2 * 9 + ij) * O_ + o]
                    + kv3 * cogs[(3 * 9 + ij) * O_ + o];
            float sg = 1.f / (1.f + expf(-s));
            float v  = sg * g_wT[((size_t)c * 9 + ij) * O_ + o];
            g_dynw[(((size_t)b * C_ + c) * 9 + ij) * O_ + o] = v;
        }
    }
}

// ---------------- K5: per-sample 3x3 conv with dynamic weights --------------
// Block tile: 64 o  x  8 rows x 14 cols.  128 threads, 8 o x 7 px per thread.
__global__ __launch_bounds__(128, 1)
void conv_kernel(const float* __restrict__ x, float* __restrict__ out) {
    const int sp = blockIdx.x;                 // 0..27
    const int rt = sp >> 2;                    // 0..6 row tile
    const int ct = sp & 3;                     // 0..3 col tile
    const int bo = blockIdx.y;                 // 0..127
    const int b  = bo >> 2;
    const int ot = bo & 3;
    const int row0 = rt * 8;
    const int col0 = ct * 14;
    const int o0   = ot * 64;

    const int tid = threadIdx.x;
    const int og  = tid >> 4;                  // 0..7  -> o base = o0 + og*8
    const int rem = tid & 15;
    const int pr  = rem >> 1;                  // 0..7  -> row = row0 + pr
    const int ph  = rem & 1;                   // 0..1  -> cols col0 + ph*7 + 0..6

    __shared__ float xs[16][10][17];           // [c][row][col(pad)]   10.88 KB
    __shared__ float ws[16 * 9][64];           // [cc*9+ij][o]         36.86 KB

    float acc[8][7];
    #pragma unroll
    for (int k = 0; k < 8; k++)
        #pragma unroll
        for (int p = 0; p < 7; p++) acc[k][p] = 0.f;

    for (int c0 = 0; c0 < C_; c0 += 16) {
        // --- stage x tile: 16c x 10r x 16cols, zero-padded halo ---
        for (int e = tid; e < 16 * 10 * 16; e += 128) {
            int cc = e / 160;
            int r2 = e - cc * 160;
            int r  = r2 >> 4;
            int col = r2 & 15;
            int gr = row0 - 1 + r;
            int gc = col0 - 1 + col;
            float v = 0.f;
            if ((unsigned)gr < HH && (unsigned)gc < WW)
                v = x[(((size_t)b * C_ + c0 + cc) * HH + gr) * WW + gc];
            xs[cc][r][col] = v;
        }
        // --- stage dyn weights: 16c x 9 x 64o  (coalesced, conflict-free) ---
        const float* wp = g_dynw + ((size_t)b * C_ + c0) * 9 * O_ + o0;
        for (int e = tid; e < 16 * 9 * 64; e += 128) {
            int o    = e & 63;
            int rest = e >> 6;                 // cc*9+ij
            ws[rest][o] = wp[(size_t)rest * O_ + o];
        }
        __syncthreads();

        #pragma unroll 2
        for (int cc = 0; cc < 16; cc++) {
            #pragma unroll
            for (int i = 0; i < 3; i++) {
                float xv[9];
                #pragma unroll
                for (int q = 0; q < 9; q++)
                    xv[q] = xs[cc][pr + i][ph * 7 + q];
                #pragma unroll
                for (int j = 0; j < 3; j++) {
                    const float* wrow = &ws[cc * 9 + i * 3 + j][og * 8];
                    float4 w0 = *(const float4*)(wrow);
                    float4 w1 = *(const float4*)(wrow + 4);
                    float wv[8] = {w0.x, w0.y, w0.z, w0.w,
                                   w1.x, w1.y, w1.z, w1.w};
                    #pragma unroll
                    for (int k = 0; k < 8; k++)
                        #pragma unroll
                        for (int p = 0; p < 7; p++)
                            acc[k][p] += wv[k] * xv[j + p];
                }
            }
        }
        __syncthreads();
    }

    // --- store ---
    const int row = row0 + pr;
    #pragma unroll
    for (int k = 0; k < 8; k++) {
        int o = o0 + og * 8 + k;
        float* op = out + (((size_t)b * O_ + o) * HH + row) * WW + col0 + ph * 7;
        #pragma unroll
        for (int p = 0; p < 7; p++) op[p] = acc[k][p];
    }
}

// ---------------- launch -----------------------------------------------------
extern "C" void kernel_launch(void* const* d_in, const int* in_sizes, int n_in,
                              void* d_out, int out_size) {
    const float* x    = (const float*)d_in[0];   // [32,256,56,56]
    const float* fc1w = (const float*)d_in[1];   // [256,256]
    const float* fc2w = (const float*)d_in[2];   // [1024,256]
    const float* fc2b = (const float*)d_in[3];   // [1024]
    const float* cog  = (const float*)d_in[4];   // [256,4,3,3]
    const float* w    = (const float*)d_in[5];   // [256,256,3,3]
    float* out = (float*)d_out;                  // [32,256,56,56]

    pool_kernel<<<B_ * C_, 256>>>(x);
    fc_kernel<<<B_, 256>>>(fc1w, fc2w, fc2b);
    wt_kernel<<<(O_ * C_ * 9) / 256, 256>>>(w);
    dynw_kernel<<<B_ * 32, 256>>>(cog);
    dim3 grid(28, 128);
    conv_kernel<<<grid, 128>>>(x, out);
}

// round 5
// speedup vs baseline: 1.0708x; 1.0708x over previous
#include <cuda_runtime.h>
#include <cuda_bf16.h>
#include <math.h>

// Problem constants
#define B_  32
#define C_  256
#define O_  256
#define HH  56
#define WW  56
#define CH_ 4

typedef unsigned long long u64;

// ---------------- device scratch (static: no dynamic allocation allowed) ----
__device__ float g_pooled[B_ * C_];            // [b][c]
__device__ float g_kern  [B_ * C_ * CH_];      // [b][c*4+ch]
__device__ float g_wT    [C_ * 9 * O_];        // [c][ij][o]  (transposed weight)
__device__ float g_dynw  [(size_t)B_ * C_ * 9 * O_]; // [b][c][ij][o]  (75.5 MB)

// ---------------- packed f32x2 helpers (Blackwell sm_100+) ------------------
__device__ __forceinline__ u64 bcast_f32x2(float x) {
    u64 r;
    asm("mov.b64 %0, {%1, %1};" : "=l"(r) : "r"(__float_as_uint(x)));
    return r;
}
__device__ __forceinline__ void fma_f32x2(u64& acc, u64 a, u64 b) {
    asm("fma.rn.f32x2 %0, %1, %2, %0;" : "+l"(acc) : "l"(a), "l"(b));
}
__device__ __forceinline__ void unpack_f32x2(u64 v, float& lo, float& hi) {
    unsigned a, b;
    asm("mov.b64 {%0, %1}, %2;" : "=r"(a), "=r"(b) : "l"(v));
    lo = __uint_as_float(a);
    hi = __uint_as_float(b);
}

// ---------------- K1: global average pool ----------------------------------
__global__ void pool_kernel(const float* __restrict__ x) {
    int bc = blockIdx.x;                       // b*256 + c
    const float* p = x + (size_t)bc * (HH * WW);
    float s = 0.f;
    for (int i = threadIdx.x; i < HH * WW; i += 256) s += p[i];
    __shared__ float red[256];
    red[threadIdx.x] = s;
    __syncthreads();
    for (int st = 128; st > 0; st >>= 1) {
        if (threadIdx.x < st) red[threadIdx.x] += red[threadIdx.x + st];
        __syncthreads();
    }
    if (threadIdx.x == 0) g_pooled[bc] = red[0] * (1.f / (HH * WW));
}

// ---------------- K2: fc1(relu) + fc2 fused, one block per batch -----------
__global__ void fc_kernel(const float* __restrict__ fc1w,
                          const float* __restrict__ fc2w,
                          const float* __restrict__ fc2b) {
    int b = blockIdx.x, t = threadIdx.x;       // 256 threads
    __shared__ float sp[C_], sh[C_];
    sp[t] = g_pooled[b * C_ + t];
    __syncthreads();
    float d = 0.f;
    const float* w1 = fc1w + t * C_;
    #pragma unroll 8
    for (int k = 0; k < C_; k++) d += sp[k] * w1[k];
    sh[t] = fmaxf(d, 0.f);
    __syncthreads();
    #pragma unroll
    for (int r = 0; r < 4; r++) {
        int j = r * 256 + t;                   // j < 1024
        const float* w2 = fc2w + j * C_;
        float d2 = fc2b[j];
        #pragma unroll 8
        for (int k = 0; k < C_; k++) d2 += sh[k] * w2[k];
        g_kern[b * (C_ * CH_) + j] = d2;
    }
}

// ---------------- K2.5: transpose static weight [o][c][ij] -> [c][ij][o] ----
__global__ void wt_kernel(const float* __restrict__ w) {
    int e = blockIdx.x * 256 + threadIdx.x;    // < 256*256*9 = 589824
    int o = e / (C_ * 9);
    int rem = e - o * (C_ * 9);                // c*9+ij
    g_wT[(size_t)rem * O_ + o] = w[e];
}

// ---------------- K3: dynamic weight generation -----------------------------
// dynw[b][c][ij][o] = sigmoid( sum_ch kern[b,c,ch]*cog[o,ch,ij] ) * weight[o,c,ij]
__global__ void dynw_kernel(const float* __restrict__ cog) {
    int blk = blockIdx.x;                      // 32*32 blocks
    int b = blk >> 5;
    int cg = blk & 31;                         // c group of 8
    int o = threadIdx.x;                       // 256 threads
    __shared__ float cogs[CH_ * 9 * O_];       // [ch*9+ij][o], 36.9 KB
    for (int e = o; e < CH_ * 9 * O_; e += 256) {
        int k  = e >> 8;                       // ch*9+ij
        int oo = e & 255;
        cogs[e] = cog[oo * (CH_ * 9) + k];
    }
    __syncthreads();
    for (int cl = 0; cl < 8; cl++) {
        int c = cg * 8 + cl;
        const float* kp = g_kern + b * (C_ * CH_) + c * CH_;
        float kv0 = kp[0], kv1 = kp[1], kv2 = kp[2], kv3 = kp[3];
        #pragma unroll
        for (int ij = 0; ij < 9; ij++) {
            float s = kv0 * cogs[(0 * 9 + ij) * O_ + o]
                    + kv1 * cogs[(1 * 9 + ij) * O_ + o]
                    + kv2 * cogs[(2 * 9 + ij) * O_ + o]
                    + kv3 * cogs[(3 * 9 + ij) * O_ + o];
            float sg = 1.f / (1.f + expf(-s));
            float v  = sg * g_wT[((size_t)c * 9 + ij) * O_ + o];
            g_dynw[(((size_t)b * C_ + c) * 9 + ij) * O_ + o] = v;
        }
    }
}

// ---------------- K5: per-sample 3x3 conv, packed f32x2 FFMA ---------------
// Block tile: 64 o  x  8 rows x 14 cols.  128 threads.
// Per thread: 8 o (as 4 packed o-pairs) x 7 px = 28 f32x2 accumulators.
__global__ __launch_bounds__(128, 1)
void conv_kernel(const float* __restrict__ x, float* __restrict__ out) {
    const int sp = blockIdx.x;                 // 0..27
    const int rt = sp >> 2;                    // 0..6 row tile
    const int ct = sp & 3;                     // 0..3 col tile
    const int bo = blockIdx.y;                 // 0..127
    const int b  = bo >> 2;
    const int ot = bo & 3;
    const int row0 = rt * 8;
    const int col0 = ct * 14;
    const int o0   = ot * 64;

    const int tid = threadIdx.x;
    const int og  = tid >> 4;                  // 0..7  -> o base = o0 + og*8
    const int rem = tid & 15;
    const int pr  = rem >> 1;                  // 0..7  -> row = row0 + pr
    const int ph  = rem & 1;                   // 0..1  -> cols col0 + ph*7 + 0..6

    __shared__ float xs[16][10][17];           // [c][row][col(pad)]   10.88 KB
    __shared__ float ws[16 * 9][64];           // [cc*9+ij][o]         36.86 KB

    u64 acc[4][7];                             // [o-pair][px], lo = even o
    #pragma unroll
    for (int k = 0; k < 4; k++)
        #pragma unroll
        for (int p = 0; p < 7; p++) acc[k][p] = 0ull;

    for (int c0 = 0; c0 < C_; c0 += 16) {
        // --- stage x tile: 16c x 10r x 16cols, zero-padded halo ---
        for (int e = tid; e < 16 * 10 * 16; e += 128) {
            int cc = e / 160;
            int r2 = e - cc * 160;
            int r  = r2 >> 4;
            int col = r2 & 15;
            int gr = row0 - 1 + r;
            int gc = col0 - 1 + col;
            float v = 0.f;
            if ((unsigned)gr < HH && (unsigned)gc < WW)
                v = x[(((size_t)b * C_ + c0 + cc) * HH + gr) * WW + gc];
            xs[cc][r][col] = v;
        }
        // --- stage dyn weights: 16c x 9 x 64o  (coalesced, conflict-free) ---
        const float* wp = g_dynw + ((size_t)b * C_ + c0) * 9 * O_ + o0;
        for (int e = tid; e < 16 * 9 * 64; e += 128) {
            int o    = e & 63;
            int rest = e >> 6;                 // cc*9+ij
            ws[rest][o] = wp[(size_t)rest * O_ + o];
        }
        __syncthreads();

        #pragma unroll 2
        for (int cc = 0; cc < 16; cc++) {
            #pragma unroll
            for (int i = 0; i < 3; i++) {
                u64 xv2[9];
                #pragma unroll
                for (int q = 0; q < 9; q++)
                    xv2[q] = bcast_f32x2(xs[cc][pr + i][ph * 7 + q]);
                #pragma unroll
                for (int j = 0; j < 3; j++) {
                    const u64* wrow =
                        (const u64*)&ws[cc * 9 + i * 3 + j][og * 8];
                    u64 w0 = wrow[0], w1 = wrow[1], w2 = wrow[2], w3 = wrow[3];
                    #pragma unroll
                    for (int p = 0; p < 7; p++) {
                        fma_f32x2(acc[0][p], w0, xv2[j + p]);
                        fma_f32x2(acc[1][p], w1, xv2[j + p]);
                        fma_f32x2(acc[2][p], w2, xv2[j + p]);
                        fma_f32x2(acc[3][p], w3, xv2[j + p]);
                    }
                }
            }
        }
        __syncthreads();
    }

    // --- store: acc[k] holds o-pair (o0+og*8+2k, +2k+1) ---
    const int row = row0 + pr;
    #pragma unroll
    for (int k = 0; k < 4; k++) {
        int o = o0 + og * 8 + 2 * k;
        float* op0 = out + (((size_t)b * O_ + o) * HH + row) * WW + col0 + ph * 7;
        float* op1 = op0 + (size_t)HH * WW;
        #pragma unroll
        for (int p = 0; p < 7; p++) {
            float lo, hi;
            unpack_f32x2(acc[k][p], lo, hi);
            op0[p] = lo;
            op1[p] = hi;
        }
    }
}

// ---------------- launch -----------------------------------------------------
extern "C" void kernel_launch(void* const* d_in, const int* in_sizes, int n_in,
                              void* d_out, int out_size) {
    const float* x    = (const float*)d_in[0];   // [32,256,56,56]
    const float* fc1w = (const float*)d_in[1];   // [256,256]
    const float* fc2w = (const float*)d_in[2];   // [1024,256]
    const float* fc2b = (const float*)d_in[3];   // [1024]
    const float* cog  = (const float*)d_in[4];   // [256,4,3,3]
    const float* w    = (const float*)d_in[5];   // [256,256,3,3]
    float* out = (float*)d_out;                  // [32,256,56,56]

    pool_kernel<<<B_ * C_, 256>>>(x);
    fc_kernel<<<B_, 256>>>(fc1w, fc2w, fc2b);
    wt_kernel<<<(O_ * C_ * 9) / 256, 256>>>(w);
    dynw_kernel<<<B_ * 32, 256>>>(cog);
    dim3 grid(28, 128);
    conv_kernel<<<grid, 128>>>(x, out);
}

// round 6
// speedup vs baseline: 3.0337x; 2.8332x over previous
#include <cuda_runtime.h>
#include <cuda_bf16.h>
#include <math.h>

// Problem constants
#define B_  32
#define C_  256
#define O_  256
#define HH  56
#define WW  56
#define CH_ 4

typedef unsigned int u32;

// ---------------- device scratch (no dynamic allocation allowed) ------------
__device__ float g_pooled[B_ * C_];            // [b][c]
__device__ float g_kern  [B_ * C_ * CH_];      // [b][c*4+ch]
__device__ float g_wT    [C_ * 9 * O_];        // [c][ij][o]
__device__ float g_dynw  [(size_t)B_ * C_ * 9 * O_]; // [b][k=c*9+ij][o], tf32-rounded

// ---------------- helpers ---------------------------------------------------
__device__ __forceinline__ u32 f2tf32(float x) {
    u32 r;
    asm("cvt.rna.tf32.f32 %0, %1;" : "=r"(r) : "f"(x));
    return r;
}
__device__ __forceinline__ u32 smem_u32(const void* p) {
    return (u32)__cvta_generic_to_shared(p);
}
__device__ __forceinline__ void cp16(u32 dst, const void* src) {
    asm volatile("cp.async.cg.shared.global [%0], [%1], 16;" :: "r"(dst), "l"(src));
}
__device__ __forceinline__ void cp4z(u32 dst, const void* src, int srcsize) {
    asm volatile("cp.async.ca.shared.global [%0], [%1], 4, %2;"
                 :: "r"(dst), "l"(src), "r"(srcsize));
}
__device__ __forceinline__ void cp_commit() {
    asm volatile("cp.async.commit_group;");
}
template <int N> __device__ __forceinline__ void cp_wait() {
    asm volatile("cp.async.wait_group %0;" :: "n"(N));
}
__device__ __forceinline__ void mma_tf32(float* c, const u32* a, u32 b0, u32 b1) {
    asm volatile(
        "mma.sync.aligned.m16n8k8.row.col.f32.tf32.tf32.f32 "
        "{%0,%1,%2,%3}, {%4,%5,%6,%7}, {%8,%9}, {%0,%1,%2,%3};"
        : "+f"(c[0]), "+f"(c[1]), "+f"(c[2]), "+f"(c[3])
        : "r"(a[0]), "r"(a[1]), "r"(a[2]), "r"(a[3]), "r"(b0), "r"(b1));
}

// ---------------- K1: global average pool ----------------------------------
__global__ void pool_kernel(const float* __restrict__ x) {
    int bc = blockIdx.x;
    const float* p = x + (size_t)bc * (HH * WW);
    float s = 0.f;
    for (int i = threadIdx.x; i < HH * WW; i += 256) s += p[i];
    __shared__ float red[256];
    red[threadIdx.x] = s;
    __syncthreads();
    for (int st = 128; st > 0; st >>= 1) {
        if (threadIdx.x < st) red[threadIdx.x] += red[threadIdx.x + st];
        __syncthreads();
    }
    if (threadIdx.x == 0) g_pooled[bc] = red[0] * (1.f / (HH * WW));
}

// ---------------- K2: fc1(relu) + fc2 fused ---------------------------------
__global__ void fc_kernel(const float* __restrict__ fc1w,
                          const float* __restrict__ fc2w,
                          const float* __restrict__ fc2b) {
    int b = blockIdx.x, t = threadIdx.x;
    __shared__ float sp[C_], sh[C_];
    sp[t] = g_pooled[b * C_ + t];
    __syncthreads();
    float d = 0.f;
    const float* w1 = fc1w + t * C_;
    #pragma unroll 8
    for (int k = 0; k < C_; k++) d += sp[k] * w1[k];
    sh[t] = fmaxf(d, 0.f);
    __syncthreads();
    #pragma unroll
    for (int r = 0; r < 4; r++) {
        int j = r * 256 + t;
        const float* w2 = fc2w + j * C_;
        float d2 = fc2b[j];
        #pragma unroll 8
        for (int k = 0; k < C_; k++) d2 += sh[k] * w2[k];
        g_kern[b * (C_ * CH_) + j] = d2;
    }
}

// ---------------- K2.5: transpose weight [o][c][ij] -> [c*9+ij][o] ----------
__global__ void wt_kernel(const float* __restrict__ w) {
    int e = blockIdx.x * 256 + threadIdx.x;
    int o = e / (C_ * 9);
    int rem = e - o * (C_ * 9);
    g_wT[(size_t)rem * O_ + o] = w[e];
}

// ---------------- K3: dynamic weights (tf32-rounded) ------------------------
__global__ void dynw_kernel(const float* __restrict__ cog) {
    int blk = blockIdx.x;
    int b = blk >> 5;
    int cg = blk & 31;
    int o = threadIdx.x;
    __shared__ float cogs[CH_ * 9 * O_];
    for (int e = o; e < CH_ * 9 * O_; e += 256) {
        int k  = e >> 8;
        int oo = e & 255;
        cogs[e] = cog[oo * (CH_ * 9) + k];
    }
    __syncthreads();
    for (int cl = 0; cl < 8; cl++) {
        int c = cg * 8 + cl;
        const float* kp = g_kern + b * (C_ * CH_) + c * CH_;
        float kv0 = kp[0], kv1 = kp[1], kv2 = kp[2], kv3 = kp[3];
        #pragma unroll
        for (int ij = 0; ij < 9; ij++) {
            float s = kv0 * cogs[(0 * 9 + ij) * O_ + o]
                    + kv1 * cogs[(1 * 9 + ij) * O_ + o]
                    + kv2 * cogs[(2 * 9 + ij) * O_ + o]
                    + kv3 * cogs[(3 * 9 + ij) * O_ + o];
            float sg = 1.f / (1.f + expf(-s));
            float v  = sg * g_wT[((size_t)c * 9 + ij) * O_ + o];
            u32 tv = f2tf32(v);
            g_dynw[(((size_t)b * C_ + c) * 9 + ij) * O_ + o] = __uint_as_float(tv);
        }
    }
}

// ---------------- K5: implicit-GEMM conv with tf32 mma.sync -----------------
// Per block: b, o-tile(128), row-group(4 rows) x 56 cols.
// 8 warps: wm = wid&1 (64 o), wn = wid>>1 (1 row of 56 px).
// K loop: 32 chunks of 8 channels (72 k each), double-buffered cp.async.
#define CCHUNK   8
#define KK       72            // CCHUNK*9
#define SA_PITCH 136           // padded row (floats) -> conflict-free frag loads
#define SA_FLTS  (KK * SA_PITCH)          // 9792
#define XS_PITCH 59
#define XS_FLTS  (CCHUNK * 6 * XS_PITCH)  // 2832
#define STAGE_FLTS (SA_FLTS + XS_FLTS)    // 12624
#define SMEM_BYTES (2 * STAGE_FLTS * 4)   // 100992

extern __shared__ float cv_smem[];

__device__ __forceinline__ void stage_chunk(const float* __restrict__ x,
                                            int b, int o0, int r0,
                                            int chunk, int buf, int tid) {
    float* sA = cv_smem + buf * STAGE_FLTS;
    float* xs = sA + SA_FLTS;
    // A: 72 rows x 128 floats, rows contiguous in g_dynw[b][k][o0..o0+127]
    const float* asrc = g_dynw + ((size_t)b * (C_ * 9) + chunk * KK) * O_ + o0;
    #pragma unroll
    for (int e = tid; e < KK * 32; e += 256) {     // float4 elements
        int kk = e >> 5;
        int q  = e & 31;
        cp16(smem_u32(sA + kk * SA_PITCH + q * 4), asrc + kk * O_ + q * 4);
    }
    // x: 8c x 6 rows x 58 cols (halo, zero-filled OOB)
    int c0 = chunk * CCHUNK;
    for (int e = tid; e < CCHUNK * 6 * 58; e += 256) {
        int cc = e / 348;
        int r2 = e - cc * 348;
        int rr = r2 / 58;
        int cx = r2 - rr * 58;
        int gr = r0 - 1 + rr;
        int gc = cx - 1;
        bool ok = ((unsigned)gr < HH) & ((unsigned)gc < WW);
        const float* src = ok
            ? x + (((size_t)b * C_ + c0 + cc) * HH + gr) * WW + gc
            : x;
        cp4z(smem_u32(xs + cc * (6 * XS_PITCH) + rr * XS_PITCH + cx),
             src, ok ? 4 : 0);
    }
}

__global__ __launch_bounds__(256, 1)
void conv_kernel(const float* __restrict__ x, float* __restrict__ out) {
    const int rg = blockIdx.x;                 // 0..13 row group (4 rows)
    const int ot = blockIdx.y;                 // 0..1
    const int b  = blockIdx.z;                 // 0..31
    const int r0 = rg * 4;
    const int o0 = ot * 128;

    const int tid  = threadIdx.x;
    const int wid  = tid >> 5;
    const int lane = tid & 31;
    const int wm = wid & 1;                    // o-half
    const int wn = wid >> 1;                   // row within group (0..3)
    const int grp = lane >> 2;                 // 0..7
    const int qid = lane & 3;                  // 0..3

    float acc[4][7][4];
    #pragma unroll
    for (int mt = 0; mt < 4; mt++)
        #pragma unroll
        for (int nt = 0; nt < 7; nt++)
            #pragma unroll
            for (int r = 0; r < 4; r++) acc[mt][nt][r] = 0.f;

    stage_chunk(x, b, o0, r0, 0, 0, tid);
    cp_commit();

    for (int it = 0; it < 32; it++) {
        const int buf = it & 1;
        if (it + 1 < 32) {
            stage_chunk(x, b, o0, r0, it + 1, buf ^ 1, tid);
            cp_commit();
            cp_wait<1>();
        } else {
            cp_wait<0>();
        }
        __syncthreads();

        const float* sA = cv_smem + buf * STAGE_FLTS;
        const float* xs = sA + SA_FLTS;

        #pragma unroll
        for (int ks = 0; ks < 9; ks++) {
            const int kb = ks * 8;
            const int k0 = kb + qid;
            const int k1 = k0 + 4;
            // A fragments (tf32 already)
            const u32* sa0 = (const u32*)(sA + k0 * SA_PITCH) + wm * 64 + grp;
            const u32* sa1 = (const u32*)(sA + k1 * SA_PITCH) + wm * 64 + grp;
            u32 a[4][4];
            #pragma unroll
            for (int mt = 0; mt < 4; mt++) {
                a[mt][0] = sa0[mt * 16];
                a[mt][1] = sa0[mt * 16 + 8];
                a[mt][2] = sa1[mt * 16];
                a[mt][3] = sa1[mt * 16 + 8];
            }
            // B offsets: k -> (cc, i, j);  xs[cc][wn+i][n+j]
            const int cc0 = k0 / 9, ij0 = k0 - cc0 * 9;
            const int cc1 = k1 / 9, ij1 = k1 - cc1 * 9;
            const int off0 = cc0 * (6 * XS_PITCH) + (wn + ij0 / 3) * XS_PITCH + (ij0 % 3);
            const int off1 = cc1 * (6 * XS_PITCH) + (wn + ij1 / 3) * XS_PITCH + (ij1 % 3);
            #pragma unroll
            for (int nt = 0; nt < 7; nt++) {
                const int n = nt * 8 + grp;
                u32 b0 = f2tf32(xs[off0 + n]);
                u32 b1 = f2tf32(xs[off1 + n]);
                #pragma unroll
                for (int mt = 0; mt < 4; mt++)
                    mma_tf32(acc[mt][nt], a[mt], b0, b1);
            }
        }
        __syncthreads();
    }

    // --- epilogue ---
    const int row = r0 + wn;
    #pragma unroll
    for (int mt = 0; mt < 4; mt++) {
        const int o_lo = o0 + wm * 64 + mt * 16 + grp;
        float* p0 = out + (((size_t)b * O_ + o_lo) * HH + row) * WW;
        float* p1 = p0 + (size_t)8 * HH * WW;          // o_lo + 8
        #pragma unroll
        for (int nt = 0; nt < 7; nt++) {
            const int col = nt * 8 + qid * 2;
            *(float2*)(p0 + col) = make_float2(acc[mt][nt][0], acc[mt][nt][1]);
            *(float2*)(p1 + col) = make_float2(acc[mt][nt][2], acc[mt][nt][3]);
        }
    }
}

// ---------------- launch -----------------------------------------------------
extern "C" void kernel_launch(void* const* d_in, const int* in_sizes, int n_in,
                              void* d_out, int out_size) {
    const float* x    = (const float*)d_in[0];   // [32,256,56,56]
    const float* fc1w = (const float*)d_in[1];   // [256,256]
    const float* fc2w = (const float*)d_in[2];   // [1024,256]
    const float* fc2b = (const float*)d_in[3];   // [1024]
    const float* cog  = (const float*)d_in[4];   // [256,4,3,3]
    const float* w    = (const float*)d_in[5];   // [256,256,3,3]
    float* out = (float*)d_out;                  // [32,256,56,56]

    cudaFuncSetAttribute(conv_kernel,
                         cudaFuncAttributeMaxDynamicSharedMemorySize, SMEM_BYTES);

    pool_kernel<<<B_ * C_, 256>>>(x);
    fc_kernel<<<B_, 256>>>(fc1w, fc2w, fc2b);
    wt_kernel<<<(O_ * C_ * 9) / 256, 256>>>(w);
    dynw_kernel<<<B_ * 32, 256>>>(cog);
    dim3 grid(14, 2, 32);
    conv_kernel<<<grid, 256, SMEM_BYTES>>>(x, out);
}

// round 9
// speedup vs baseline: 3.1208x; 1.0287x over previous
#include <cuda_runtime.h>
#include <cuda_bf16.h>
#include <math.h>

// Problem constants
#define B_  32
#define C_  256
#define O_  256
#define HH  56
#define WW  56
#define CH_ 4

typedef unsigned int u32;

// ---------------- device scratch (no dynamic allocation allowed) ------------
__device__ float g_pooled[B_ * C_];            // [b][c]
__device__ float g_kern  [B_ * C_ * CH_];      // [b][c*4+ch]
__device__ float g_wT    [C_ * 9 * O_];        // [c][ij][o]
__device__ float g_dynw  [(size_t)B_ * C_ * 9 * O_]; // [b][k=c*9+ij][o], tf32-rounded

// ---------------- helpers ---------------------------------------------------
__device__ __forceinline__ u32 f2tf32(float x) {
    u32 r;
    asm("cvt.rna.tf32.f32 %0, %1;" : "=r"(r) : "f"(x));
    return r;
}
__device__ __forceinline__ u32 smem_u32(const void* p) {
    return (u32)__cvta_generic_to_shared(p);
}
__device__ __forceinline__ void cp16(u32 dst, const void* src) {
    asm volatile("cp.async.cg.shared.global [%0], [%1], 16;" :: "r"(dst), "l"(src));
}
__device__ __forceinline__ void cp_commit() {
    asm volatile("cp.async.commit_group;");
}
template <int N> __device__ __forceinline__ void cp_wait() {
    asm volatile("cp.async.wait_group %0;" :: "n"(N));
}
__device__ __forceinline__ void mma_tf32(float* c, const u32* a, u32 b0, u32 b1) {
    asm volatile(
        "mma.sync.aligned.m16n8k8.row.col.f32.tf32.tf32.f32 "
        "{%0,%1,%2,%3}, {%4,%5,%6,%7}, {%8,%9}, {%0,%1,%2,%3};"
        : "+f"(c[0]), "+f"(c[1]), "+f"(c[2]), "+f"(c[3])
        : "r"(a[0]), "r"(a[1]), "r"(a[2]), "r"(a[3]), "r"(b0), "r"(b1));
}

// ---------------- K1: global average pool ----------------------------------
__global__ void pool_kernel(const float* __restrict__ x) {
    int bc = blockIdx.x;
    const float* p = x + (size_t)bc * (HH * WW);
    float s = 0.f;
    for (int i = threadIdx.x; i < HH * WW; i += 256) s += p[i];
    __shared__ float red[256];
    red[threadIdx.x] = s;
    __syncthreads();
    for (int st = 128; st > 0; st >>= 1) {
        if (threadIdx.x < st) red[threadIdx.x] += red[threadIdx.x + st];
        __syncthreads();
    }
    if (threadIdx.x == 0) g_pooled[bc] = red[0] * (1.f / (HH * WW));
}

// ---------------- K2: fc1(relu) + fc2 fused ---------------------------------
__global__ void fc_kernel(const float* __restrict__ fc1w,
                          const float* __restrict__ fc2w,
                          const float* __restrict__ fc2b) {
    int b = blockIdx.x, t = threadIdx.x;
    __shared__ float sp[C_], sh[C_];
    sp[t] = g_pooled[b * C_ + t];
    __syncthreads();
    float d = 0.f;
    const float* w1 = fc1w + t * C_;
    #pragma unroll 8
    for (int k = 0; k < C_; k++) d += sp[k] * w1[k];
    sh[t] = fmaxf(d, 0.f);
    __syncthreads();
    #pragma unroll
    for (int r = 0; r < 4; r++) {
        int j = r * 256 + t;
        const float* w2 = fc2w + j * C_;
        float d2 = fc2b[j];
        #pragma unroll 8
        for (int k = 0; k < C_; k++) d2 += sh[k] * w2[k];
        g_kern[b * (C_ * CH_) + j] = d2;
    }
}

// ---------------- K2.5: transpose weight [o][c][ij] -> [c*9+ij][o] ----------
__global__ void wt_kernel(const float* __restrict__ w) {
    int e = blockIdx.x * 256 + threadIdx.x;
    int o = e / (C_ * 9);
    int rem = e - o * (C_ * 9);
    g_wT[(size_t)rem * O_ + o] = w[e];
}

// ---------------- K3: dynamic weights (tf32-rounded) ------------------------
__global__ void dynw_kernel(const float* __restrict__ cog) {
    int blk = blockIdx.x;
    int b = blk >> 5;
    int cg = blk & 31;
    int o = threadIdx.x;
    __shared__ float cogs[CH_ * 9 * O_];
    for (int e = o; e < CH_ * 9 * O_; e += 256) {
        int k  = e >> 8;
        int oo = e & 255;
        cogs[e] = cog[oo * (CH_ * 9) + k];
    }
    __syncthreads();
    for (int cl = 0; cl < 8; cl++) {
        int c = cg * 8 + cl;
        const float* kp = g_kern + b * (C_ * CH_) + c * CH_;
        float kv0 = kp[0], kv1 = kp[1], kv2 = kp[2], kv3 = kp[3];
        #pragma unroll
        for (int ij = 0; ij < 9; ij++) {
            float s = kv0 * cogs[(0 * 9 + ij) * O_ + o]
                    + kv1 * cogs[(1 * 9 + ij) * O_ + o]
                    + kv2 * cogs[(2 * 9 + ij) * O_ + o]
                    + kv3 * cogs[(3 * 9 + ij) * O_ + o];
            float sg = 1.f / (1.f + expf(-s));
            float v  = sg * g_wT[((size_t)c * 9 + ij) * O_ + o];
            u32 tv = f2tf32(v);
            g_dynw[(((size_t)b * C_ + c) * 9 + ij) * O_ + o] = __uint_as_float(tv);
        }
    }
}

// ---------------- K5: implicit-GEMM conv with tf32 mma.sync -----------------
// Block: 64 o x 4 rows x 56 px, 256 thr (8 warps), 2 blocks/SM.
// Warp: wm = wid&1 -> 32 o, wn = wid>>1 -> 1 row of 56 px (7 n-tiles).
// K loop: 32 chunks of 8 channels (72 k), double-buffered cp.async.
#define CCHUNK   8
#define KK       72            // CCHUNK*9
#define SA_PITCH 72            // 72 mod 32 = 8 -> conflict-free frag loads
#define SA_FLTS  (KK * SA_PITCH)          // 5184
#define XS_PITCH 68            // data at [4..59]; [3],[60] are persistent zeros
#define XS_FLTS  (CCHUNK * 6 * XS_PITCH)  // 3264
#define STAGE_FLTS (SA_FLTS + XS_FLTS)    // 8448
#define SMEM_BYTES (2 * STAGE_FLTS * 4)   // 67584

extern __shared__ float cv_smem[];

__device__ __forceinline__ void stage_chunk(const float* __restrict__ x,
                                            int b, int o0, int r0,
                                            int chunk, int buf, int tid) {
    float* sA = cv_smem + buf * STAGE_FLTS;
    float* xs = sA + SA_FLTS;
    // A: 72 rows x 64 floats (16B-aligned both sides)
    const float* asrc = g_dynw + ((size_t)b * (C_ * 9) + chunk * KK) * O_ + o0;
    for (int e = tid; e < KK * 16; e += 256) {     // float4 elements
        int kk = e >> 4;
        int q  = e & 15;
        cp16(smem_u32(sA + kk * SA_PITCH + q * 4), asrc + kk * O_ + q * 4);
    }
    // x: 8c x 6 rows x 56 cols interior as cp16; halos/OOB are persistent zeros
    int c0 = chunk * CCHUNK;
    for (int e = tid; e < CCHUNK * 6 * 14; e += 256) {
        int cc = e / 84;
        int r2 = e - cc * 84;
        int rr = r2 / 14;
        int f  = r2 - rr * 14;
        int gr = r0 - 1 + rr;
        if ((unsigned)gr < HH)
            cp16(smem_u32(xs + cc * (6 * XS_PITCH) + rr * XS_PITCH + 4 + f * 4),
                 x + (((size_t)b * C_ + c0 + cc) * HH + gr) * WW + f * 4);
    }
}

__global__ __launch_bounds__(256, 2)
void conv_kernel(const float* __restrict__ x, float* __restrict__ out) {
    const int rg = blockIdx.x;                 // 0..13 (4-row group)
    const int ot = blockIdx.y;                 // 0..3  (64-o tile)
    const int b  = blockIdx.z;                 // 0..31
    const int r0 = rg * 4;
    const int o0 = ot * 64;

    const int tid  = threadIdx.x;
    const int wid  = tid >> 5;
    const int lane = tid & 31;
    const int wm = wid & 1;                    // 32-o half
    const int wn = wid >> 1;                   // row in group (0..3)
    const int grp = lane >> 2;                 // 0..7
    const int qid = lane & 3;                  // 0..3

    // zero-init both stage buffers once (persistent halo zeros)
    for (int e = tid; e < 2 * STAGE_FLTS; e += 256) cv_smem[e] = 0.f;
    __syncthreads();

    float acc[2][7][4];
    #pragma unroll
    for (int mt = 0; mt < 2; mt++)
        #pragma unroll
        for (int nt = 0; nt < 7; nt++)
            #pragma unroll
            for (int r = 0; r < 4; r++) acc[mt][nt][r] = 0.f;

    stage_chunk(x, b, o0, r0, 0, 0, tid);
    cp_commit();

    for (int it = 0; it < 32; it++) {
        const int buf = it & 1;
        if (it + 1 < 32) {
            stage_chunk(x, b, o0, r0, it + 1, buf ^ 1, tid);
            cp_commit();
            cp_wait<1>();
        } else {
            cp_wait<0>();
        }
        __syncthreads();

        const float* sA = cv_smem + buf * STAGE_FLTS;
        const float* xs = sA + SA_FLTS;

        #pragma unroll
        for (int ks = 0; ks < 9; ks++) {
            const int k0 = ks * 8 + qid;
            const int k1 = k0 + 4;
            const u32* sa0 = (const u32*)(sA + k0 * SA_PITCH) + wm * 32 + grp;
            const u32* sa1 = (const u32*)(sA + k1 * SA_PITCH) + wm * 32 + grp;
            u32 a[2][4];
            #pragma unroll
            for (int mt = 0; mt < 2; mt++) {
                a[mt][0] = sa0[mt * 16];
                a[mt][1] = sa0[mt * 16 + 8];
                a[mt][2] = sa1[mt * 16];
                a[mt][3] = sa1[mt * 16 + 8];
            }
            const int cc0 = k0 / 9, ij0 = k0 - cc0 * 9;
            const int cc1 = k1 / 9, ij1 = k1 - cc1 * 9;
            const int off0 = cc0 * (6 * XS_PITCH) + (wn + ij0 / 3) * XS_PITCH + 3 + (ij0 % 3);
            const int off1 = cc1 * (6 * XS_PITCH) + (wn + ij1 / 3) * XS_PITCH + 3 + (ij1 % 3);
            #pragma unroll
            for (int nt = 0; nt < 7; nt++) {
                const int n = nt * 8 + grp;
                u32 b0 = f2tf32(xs[off0 + n]);
                u32 b1 = f2tf32(xs[off1 + n]);
                mma_tf32(acc[0][nt], a[0], b0, b1);
                mma_tf32(acc[1][nt], a[1], b0, b1);
            }
        }
        __syncthreads();
    }

    // --- epilogue ---
    const int row = r0 + wn;
    #pragma unroll
    for (int mt = 0; mt < 2; mt++) {
        const int o_lo = o0 + wm * 32 + mt * 16 + grp;
        float* p0 = out + (((size_t)b * O_ + o_lo) * HH + row) * WW;
        float* p1 = p0 + (size_t)8 * HH * WW;          // o_lo + 8
        #pragma unroll
        for (int nt = 0; nt < 7; nt++) {
            const int col = nt * 8 + qid * 2;
            *(float2*)(p0 + col) = make_float2(acc[mt][nt][0], acc[mt][nt][1]);
            *(float2*)(p1 + col) = make_float2(acc[mt][nt][2], acc[mt][nt][3]);
        }
    }
}

// ---------------- launch -----------------------------------------------------
extern "C" void kernel_launch(void* const* d_in, const int* in_sizes, int n_in,
                              void* d_out, int out_size) {
    const float* x    = (const float*)d_in[0];   // [32,256,56,56]
    const float* fc1w = (const float*)d_in[1];   // [256,256]
    const float* fc2w = (const float*)d_in[2];   // [1024,256]
    const float* fc2b = (const float*)d_in[3];   // [1024]
    const float* cog  = (const float*)d_in[4];   // [256,4,3,3]
    const float* w    = (const float*)d_in[5];   // [256,256,3,3]
    float* out = (float*)d_out;                  // [32,256,56,56]

    cudaFuncSetAttribute(conv_kernel,
                         cudaFuncAttributeMaxDynamicSharedMemorySize, SMEM_BYTES);

    pool_kernel<<<B_ * C_, 256>>>(x);
    fc_kernel<<<B_, 256>>>(fc1w, fc2w, fc2b);
    wt_kernel<<<(O_ * C_ * 9) / 256, 256>>>(w);
    dynw_kernel<<<B_ * 32, 256>>>(cog);
    dim3 grid(14, 4, 32);
    conv_kernel<<<grid, 256, SMEM_BYTES>>>(x, out);
}